// round 3
// baseline (speedup 1.0000x reference)
#include <cuda_runtime.h>

#define HW      49
#define QP      50      // q padded to even
#define ROWF    (2*QP)  // duplicated A row length in floats (100 -> 400B, 16B aligned)
#define CCOLS   512
#define CT      128     // c-tile per CTA
#define THREADS 256

typedef unsigned long long u64;

// Packed fp32x2 FMA (Blackwell FFMA2) — only reachable via PTX.
__device__ __forceinline__ u64 fma2(u64 a, u64 b, u64 c) {
    u64 d;
    asm("fma.rn.f32x2 %0, %1, %2, %3;" : "=l"(d) : "l"(a), "l"(b), "l"(c));
    return d;
}

__device__ __forceinline__ u64 pack2(float lo, float hi) {
    u64 d;
    asm("mov.b64 %0, {%1, %2};" : "=l"(d) : "f"(lo), "f"(hi));
    return d;
}

__global__ __launch_bounds__(THREADS, 4)
void bmm_tr_residual_kernel(const float* __restrict__ x,
                            const float* __restrict__ attn,
                            const float* __restrict__ Dm,
                            const float* __restrict__ alpha,
                            float* __restrict__ out)
{
    // attn duplicated per element, rows padded to 400B so a 16B LDS.128
    // broadcast yields (a_q,a_q,a_{q+1},a_{q+1}) = two ready fma2 operands.
    __shared__ __align__(16) float sA2[HW * ROWF];   // 19600 B
    __shared__ __align__(16) float sD[QP * CT];      // 25600 B; reused as Y[c][p]

    const int n   = blockIdx.y;
    const int c0  = blockIdx.x * CT;
    const int tid = threadIdx.x;

    // ---- stage attn[n] duplicated, q padded with zeros ----
    const float* An = attn + (size_t)n * HW * HW;
    for (int i = tid; i < HW * QP; i += THREADS) {
        int p = i / QP, q = i % QP;
        float v = (q < HW) ? An[p * HW + q] : 0.0f;
        sA2[p * ROWF + 2 * q]     = v;
        sA2[p * ROWF + 2 * q + 1] = v;
    }

    // ---- stage D[n][:, c0:c0+CT] (rows padded with zeros) via float4 ----
    const float* Dn = Dm + (size_t)n * HW * CCOLS + c0;
    float4* sD4 = (float4*)sD;
    for (int i = tid; i < QP * (CT / 4); i += THREADS) {
        int q = i / (CT / 4);
        int j = i % (CT / 4);
        sD4[i] = (q < HW) ? *(const float4*)(Dn + (size_t)q * CCOLS + j * 4)
                          : make_float4(0.f, 0.f, 0.f, 0.f);
    }
    __syncthreads();

    // ---- compute: thread owns c {4tc..4tc+3}, p rows {tp+8k} ----
    const int tc = tid & 31;
    const int tp = tid >> 5;

    u64 acc[7][2];
#pragma unroll
    for (int k = 0; k < 7; ++k) { acc[k][0] = 0ull; acc[k][1] = 0ull; }

    for (int qb = 0; qb < QP / 2; ++qb) {          // 25 blocks of 2 q's
        const int q0 = 2 * qb;
        // B for both q's: one LDS.128 each (4 consecutive c)
        float4 B0 = *(const float4*)(sD + q0 * CT + 4 * tc);
        float4 B1 = *(const float4*)(sD + (q0 + 1) * CT + 4 * tc);
        u64 b00 = pack2(B0.x, B0.y), b01 = pack2(B0.z, B0.w);
        u64 b10 = pack2(B1.x, B1.y), b11 = pack2(B1.z, B1.w);
#pragma unroll
        for (int k = 0; k < 7; ++k) {
            int p = tp + 8 * k;
            u64 aLo, aHi;
            if (p < HW) {       // warp-uniform guard
                float4 A4 = *(const float4*)(sA2 + p * ROWF + 4 * qb); // 16B broadcast
                aLo = pack2(A4.x, A4.y);
                aHi = pack2(A4.z, A4.w);
            } else {
                aLo = 0ull; aHi = 0ull;
            }
            acc[k][0] = fma2(aLo, b00, acc[k][0]);
            acc[k][1] = fma2(aLo, b01, acc[k][1]);
            acc[k][0] = fma2(aHi, b10, acc[k][0]);
            acc[k][1] = fma2(aHi, b11, acc[k][1]);
        }
    }
    __syncthreads();   // all reads of sD done — safe to reuse as Y

    // ---- scatter Y into smem as [c][p] so gmem writes are contiguous ----
#pragma unroll
    for (int k = 0; k < 7; ++k) {
        int p = tp + 8 * k;
        if (p < HW) {
#pragma unroll
            for (int w = 0; w < 2; ++w) {
                int c = 4 * tc + 2 * w;
                float lo, hi;
                asm("mov.b64 {%0,%1}, %2;" : "=f"(lo), "=f"(hi) : "l"(acc[k][w]));
                sD[c * HW + p]       = lo;
                sD[(c + 1) * HW + p] = hi;
            }
        }
    }
    __syncthreads();

    // ---- residual epilogue: out[n, c0:c0+CT, :] is one contiguous CT*HW block ----
    const float  al   = alpha[0];
    const size_t base = (size_t)n * CCOLS * HW + (size_t)c0 * HW;
    const float4* x4  = (const float4*)(x + base);
    const float4* y4  = (const float4*)sD;
    float4*       o4  = (float4*)(out + base);

    for (int i = tid; i < (CT * HW) / 4; i += THREADS) {
        float4 xv = x4[i];
        float4 yv = y4[i];
        float4 ov;
        ov.x = fmaf(al, yv.x, xv.x);
        ov.y = fmaf(al, yv.y, xv.y);
        ov.z = fmaf(al, yv.z, xv.z);
        ov.w = fmaf(al, yv.w, xv.w);
        o4[i] = ov;
    }
}

extern "C" void kernel_launch(void* const* d_in, const int* in_sizes, int n_in,
                              void* d_out, int out_size)
{
    const float* x     = (const float*)d_in[0];
    const float* attn  = (const float*)d_in[1];
    const float* Dm    = (const float*)d_in[2];
    const float* alpha = (const float*)d_in[3];
    float*       out   = (float*)d_out;

    const int N = in_sizes[1] / (HW * HW);   // 2048
    dim3 grid(CCOLS / CT, N);                // (4, 2048)
    bmm_tr_residual_kernel<<<grid, THREADS>>>(x, attn, Dm, alpha, out);
}